// round 4
// baseline (speedup 1.0000x reference)
#include <cuda_runtime.h>
#include <cstdint>

// x [B=512, T=128, C=512] fp32; Wq/Wk/Wv [H=64, C=512]; out [B, T, 64] fp32.
// 128-thread CTA per batch, 2 CTAs/SM. mma.sync m16n8k8 tf32.
// S/P and Q live in registers; only K, V^T, and X/W staging tiles in smem.
#define TT 128
#define CC 512
#define HH 64
#define KT 32

// pitches (floats); pitch % 32 == 4 => conflict-free fragment access
#define PK 68
#define PVT 132
#define PT 36

#define OFF_K  0
#define OFF_VT (128 * PK)                   // 8704
#define OFF_X  (OFF_VT + 64 * PVT)          // 17152
#define OFF_W  (OFF_X + 128 * PT)           // 21760
#define SMEM_FLOATS (OFF_W + 128 * PT)      // 26368 floats = 105472 bytes

__device__ __forceinline__ float tf32r(float f) {
    uint32_t u;
    asm("cvt.rna.tf32.f32 %0, %1;" : "=r"(u) : "f"(f));
    return __uint_as_float(u);
}
__device__ __forceinline__ uint32_t tf32b(float f) {
    uint32_t u;
    asm("cvt.rna.tf32.f32 %0, %1;" : "=r"(u) : "f"(f));
    return u;
}
__device__ __forceinline__ uint32_t fb(float f) { return __float_as_uint(f); }

__device__ __forceinline__ void mma8(float* d, const uint32_t* a, const uint32_t* b) {
    asm volatile(
        "mma.sync.aligned.m16n8k8.row.col.f32.tf32.tf32.f32 "
        "{%0,%1,%2,%3}, {%4,%5,%6,%7}, {%8,%9}, {%0,%1,%2,%3};"
        : "+f"(d[0]), "+f"(d[1]), "+f"(d[2]), "+f"(d[3])
        : "r"(a[0]), "r"(a[1]), "r"(a[2]), "r"(a[3]), "r"(b[0]), "r"(b[1]));
}

// D-fragment (f32 m16n8) -> A-fragment (tf32 m16k8) lane permutation.
// D: lane(l4,lk) holds (row l4, cols 2lk,2lk+1) + (row l4+8, same) as d0..d3.
// A: lane(l4,lk) needs (l4,lk),(l4+8,lk),(l4,lk+4),(l4+8,lk+4).
__device__ __forceinline__ void d2a(const float* d, uint32_t* a,
                                    int grp, int lk, float scale) {
    const int s1 = grp + (lk >> 1);
    const int s2 = s1 + 2;
    const bool odd = lk & 1;
    float e, o;
    e = __shfl_sync(0xffffffffu, d[0], s1);
    o = __shfl_sync(0xffffffffu, d[1], s1);
    a[0] = tf32b(scale * (odd ? o : e));
    e = __shfl_sync(0xffffffffu, d[2], s1);
    o = __shfl_sync(0xffffffffu, d[3], s1);
    a[1] = tf32b(scale * (odd ? o : e));
    e = __shfl_sync(0xffffffffu, d[0], s2);
    o = __shfl_sync(0xffffffffu, d[1], s2);
    a[2] = tf32b(scale * (odd ? o : e));
    e = __shfl_sync(0xffffffffu, d[2], s2);
    o = __shfl_sync(0xffffffffu, d[3], s2);
    a[3] = tf32b(scale * (odd ? o : e));
}

__global__ __launch_bounds__(128, 2)
void attn_hmma2_kernel(const float* __restrict__ x,
                       const float* __restrict__ Wq,
                       const float* __restrict__ Wk,
                       const float* __restrict__ Wv,
                       float* __restrict__ out)
{
    extern __shared__ float sm[];
    float* Ksm = sm + OFF_K;
    float* Vt  = sm + OFF_VT;
    float* Xs  = sm + OFF_X;
    float* Wsm = sm + OFF_W;

    const int tid  = threadIdx.x;
    const int wid  = tid >> 5;
    const int lane = tid & 31;
    const int l4   = lane >> 2;
    const int lk   = lane & 3;
    const int grp  = lane & ~3;
    const int mb   = wid * 32;
    const int b    = blockIdx.x;
    const float* xb = x + (size_t)b * TT * CC;

    uint32_t qa[2][8][4];   // Q as A-fragments (scale folded in)

    // ================= Pass 1: [Q|K] = x @ [Wq|Wk]^T  (128 n-cols) =================
    {
        float acc[2][16][4];
#pragma unroll
        for (int i = 0; i < 2; i++)
#pragma unroll
            for (int j = 0; j < 16; j++)
#pragma unroll
                for (int k = 0; k < 4; k++) acc[i][j][k] = 0.0f;

#pragma unroll 1
        for (int ch = 0; ch < 16; ch++) {
            const int k0 = ch * KT;
#pragma unroll
            for (int q = 0; q < 8; q++) {         // X tile [128][32]
                int idx = q * 128 + tid;
                int row = idx >> 3, c4 = idx & 7;
                float4 v = *reinterpret_cast<const float4*>(xb + row * CC + k0 + c4 * 4);
                float4 u = { tf32r(v.x), tf32r(v.y), tf32r(v.z), tf32r(v.w) };
                *reinterpret_cast<float4*>(Xs + row * PT + c4 * 4) = u;
            }
#pragma unroll
            for (int q = 0; q < 8; q++) {         // W tile [128][32] = Wq|Wk
                int idx = q * 128 + tid;
                int row = idx >> 3, c4 = idx & 7;
                const float* Wp = (row < 64) ? (Wq + row * CC) : (Wk + (row - 64) * CC);
                float4 v = *reinterpret_cast<const float4*>(Wp + k0 + c4 * 4);
                float4 u = { tf32r(v.x), tf32r(v.y), tf32r(v.z), tf32r(v.w) };
                *reinterpret_cast<float4*>(Wsm + row * PT + c4 * 4) = u;
            }
            __syncthreads();

#pragma unroll
            for (int ks = 0; ks < 4; ks++) {
                const int kk = ks * 8;
                uint32_t a[2][4];
#pragma unroll
                for (int mt = 0; mt < 2; mt++) {
                    const float* ap = Xs + (mb + mt * 16 + l4) * PT + kk + lk;
                    a[mt][0] = fb(ap[0]);
                    a[mt][1] = fb(ap[8 * PT]);
                    a[mt][2] = fb(ap[4]);
                    a[mt][3] = fb(ap[8 * PT + 4]);
                }
#pragma unroll
                for (int nt = 0; nt < 16; nt++) {
                    const float* bp = Wsm + (nt * 8 + l4) * PT + kk + lk;
                    uint32_t b2[2] = { fb(bp[0]), fb(bp[4]) };
                    mma8(acc[0][nt], a[0], b2);
                    mma8(acc[1][nt], a[1], b2);
                }
            }
            __syncthreads();
        }

        // Q tiles (nt 0..7) -> register A-frags with attention scale 1/8 folded in
#pragma unroll
        for (int mt = 0; mt < 2; mt++)
#pragma unroll
            for (int nt = 0; nt < 8; nt++)
                d2a(acc[mt][nt], qa[mt][nt], grp, lk, 0.125f);

        // K tiles (nt 8..15) -> smem [t][h], tf32-rounded
#pragma unroll
        for (int mt = 0; mt < 2; mt++) {
            const int r0 = mb + mt * 16 + l4;
#pragma unroll
            for (int nt = 8; nt < 16; nt++) {
                const int c0 = (nt - 8) * 8 + 2 * lk;
                *reinterpret_cast<float2*>(Ksm + r0 * PK + c0) =
                    make_float2(tf32r(acc[mt][nt][0]), tf32r(acc[mt][nt][1]));
                *reinterpret_cast<float2*>(Ksm + (r0 + 8) * PK + c0) =
                    make_float2(tf32r(acc[mt][nt][2]), tf32r(acc[mt][nt][3]));
            }
        }
    }

    // ================= Pass 2: V = x @ Wv^T  (64 n-cols) =================
    {
        float accv[2][8][4];
#pragma unroll
        for (int i = 0; i < 2; i++)
#pragma unroll
            for (int j = 0; j < 8; j++)
#pragma unroll
                for (int k = 0; k < 4; k++) accv[i][j][k] = 0.0f;

#pragma unroll 1
        for (int ch = 0; ch < 16; ch++) {
            const int k0 = ch * KT;
#pragma unroll
            for (int q = 0; q < 8; q++) {
                int idx = q * 128 + tid;
                int row = idx >> 3, c4 = idx & 7;
                float4 v = *reinterpret_cast<const float4*>(xb + row * CC + k0 + c4 * 4);
                float4 u = { tf32r(v.x), tf32r(v.y), tf32r(v.z), tf32r(v.w) };
                *reinterpret_cast<float4*>(Xs + row * PT + c4 * 4) = u;
            }
#pragma unroll
            for (int q = 0; q < 4; q++) {         // Wv tile [64][32]
                int idx = q * 128 + tid;
                int row = idx >> 3, c4 = idx & 7;
                float4 v = *reinterpret_cast<const float4*>(Wv + row * CC + k0 + c4 * 4);
                float4 u = { tf32r(v.x), tf32r(v.y), tf32r(v.z), tf32r(v.w) };
                *reinterpret_cast<float4*>(Wsm + row * PT + c4 * 4) = u;
            }
            __syncthreads();

#pragma unroll
            for (int ks = 0; ks < 4; ks++) {
                const int kk = ks * 8;
                uint32_t a[2][4];
#pragma unroll
                for (int mt = 0; mt < 2; mt++) {
                    const float* ap = Xs + (mb + mt * 16 + l4) * PT + kk + lk;
                    a[mt][0] = fb(ap[0]);
                    a[mt][1] = fb(ap[8 * PT]);
                    a[mt][2] = fb(ap[4]);
                    a[mt][3] = fb(ap[8 * PT + 4]);
                }
#pragma unroll
                for (int nt = 0; nt < 8; nt++) {
                    const float* bp = Wsm + (nt * 8 + l4) * PT + kk + lk;
                    uint32_t b2[2] = { fb(bp[0]), fb(bp[4]) };
                    mma8(accv[0][nt], a[0], b2);
                    mma8(accv[1][nt], a[1], b2);
                }
            }
            __syncthreads();
        }

        // V tiles -> Vt[h][t] transposed, tf32-rounded
#pragma unroll
        for (int mt = 0; mt < 2; mt++) {
            const int r0 = mb + mt * 16 + l4;
#pragma unroll
            for (int nt = 0; nt < 8; nt++) {
                const int h0 = nt * 8 + 2 * lk;
                Vt[h0 * PVT + r0]           = tf32r(accv[mt][nt][0]);
                Vt[(h0 + 1) * PVT + r0]     = tf32r(accv[mt][nt][1]);
                Vt[h0 * PVT + r0 + 8]       = tf32r(accv[mt][nt][2]);
                Vt[(h0 + 1) * PVT + r0 + 8] = tf32r(accv[mt][nt][3]);
            }
        }
    }
    __syncthreads();   // K/Vt visible to all warps

    // ================= Phase 3+4+5: S = Q K^T, softmax, O = P V =================
    float invA[2], invB[2];
    uint32_t pa[2][16][4];   // P as A-fragments (unnormalized)

#pragma unroll
    for (int mt = 0; mt < 2; mt++) {
        float accS[16][4];
#pragma unroll
        for (int j = 0; j < 16; j++)
#pragma unroll
            for (int k = 0; k < 4; k++) accS[j][k] = 0.0f;

#pragma unroll
        for (int ks = 0; ks < 8; ks++) {
            const int kk = ks * 8;
#pragma unroll
            for (int nt = 0; nt < 16; nt++) {
                const float* bp = Ksm + (nt * 8 + l4) * PK + kk + lk;
                uint32_t b2[2] = { fb(bp[0]), fb(bp[4]) };
                mma8(accS[nt], qa[mt][ks], b2);
            }
        }

        // softmax over the two rows this thread contributes to
        const int rA = mb + mt * 16 + l4;
        const int rB = rA + 8;
        float mA = -1e30f, mB = -1e30f;
#pragma unroll
        for (int nt = 0; nt < 16; nt++) {
            const int c0 = nt * 8 + 2 * lk, c1 = c0 + 1;
            float v0 = (c0 <= rA) ? accS[nt][0] : -1e30f;
            float v1 = (c1 <= rA) ? accS[nt][1] : -1e30f;
            float v2 = (c0 <= rB) ? accS[nt][2] : -1e30f;
            float v3 = (c1 <= rB) ? accS[nt][3] : -1e30f;
            accS[nt][0] = v0; accS[nt][1] = v1; accS[nt][2] = v2; accS[nt][3] = v3;
            mA = fmaxf(mA, fmaxf(v0, v1));
            mB = fmaxf(mB, fmaxf(v2, v3));
        }
        mA = fmaxf(mA, __shfl_xor_sync(0xffffffffu, mA, 1));
        mA = fmaxf(mA, __shfl_xor_sync(0xffffffffu, mA, 2));
        mB = fmaxf(mB, __shfl_xor_sync(0xffffffffu, mB, 1));
        mB = fmaxf(mB, __shfl_xor_sync(0xffffffffu, mB, 2));

        float sA = 0.0f, sB = 0.0f;
#pragma unroll
        for (int nt = 0; nt < 16; nt++) {
            const int c0 = nt * 8 + 2 * lk, c1 = c0 + 1;
            float e0 = (c0 <= rA) ? __expf(accS[nt][0] - mA) : 0.0f;
            float e1 = (c1 <= rA) ? __expf(accS[nt][1] - mA) : 0.0f;
            float e2 = (c0 <= rB) ? __expf(accS[nt][2] - mB) : 0.0f;
            float e3 = (c1 <= rB) ? __expf(accS[nt][3] - mB) : 0.0f;
            accS[nt][0] = e0; accS[nt][1] = e1; accS[nt][2] = e2; accS[nt][3] = e3;
            sA += e0 + e1;
            sB += e2 + e3;
        }
        sA += __shfl_xor_sync(0xffffffffu, sA, 1);
        sA += __shfl_xor_sync(0xffffffffu, sA, 2);
        sB += __shfl_xor_sync(0xffffffffu, sB, 1);
        sB += __shfl_xor_sync(0xffffffffu, sB, 2);
        invA[mt] = 1.0f / sA;
        invB[mt] = 1.0f / sB;

        // P (unnormalized) -> A-fragments for PV
#pragma unroll
        for (int nt = 0; nt < 16; nt++)
            d2a(accS[nt], pa[mt][nt], grp, lk, 1.0f);
    }

    // O = P @ V, normalized at the end
    float accO[2][8][4];
#pragma unroll
    for (int i = 0; i < 2; i++)
#pragma unroll
        for (int j = 0; j < 8; j++)
#pragma unroll
            for (int k = 0; k < 4; k++) accO[i][j][k] = 0.0f;

#pragma unroll
    for (int ks = 0; ks < 16; ks++) {
        const int kk = ks * 8;
#pragma unroll
        for (int nt = 0; nt < 8; nt++) {
            const float* bp = Vt + (nt * 8 + l4) * PVT + kk + lk;
            uint32_t b2[2] = { fb(bp[0]), fb(bp[4]) };
            mma8(accO[0][nt], pa[0][ks], b2);
            mma8(accO[1][nt], pa[1][ks], b2);
        }
    }

#pragma unroll
    for (int mt = 0; mt < 2; mt++) {
        const int r0 = mb + mt * 16 + l4;
#pragma unroll
        for (int nt = 0; nt < 8; nt++) {
            const int c0 = nt * 8 + 2 * lk;
            *reinterpret_cast<float2*>(out + ((size_t)b * TT + r0) * HH + c0) =
                make_float2(accO[mt][nt][0] * invA[mt], accO[mt][nt][1] * invA[mt]);
            *reinterpret_cast<float2*>(out + ((size_t)b * TT + r0 + 8) * HH + c0) =
                make_float2(accO[mt][nt][2] * invB[mt], accO[mt][nt][3] * invB[mt]);
        }
    }
}

extern "C" void kernel_launch(void* const* d_in, const int* in_sizes, int n_in,
                              void* d_out, int out_size)
{
    const float* x  = (const float*)d_in[0];
    const float* Wq = (const float*)d_in[1];
    const float* Wk = (const float*)d_in[2];
    const float* Wv = (const float*)d_in[3];
    float* out = (float*)d_out;

    const int B = in_sizes[0] / (TT * CC);                        // 512
    const size_t smem_bytes = (size_t)SMEM_FLOATS * sizeof(float); // 105472

    cudaFuncSetAttribute(attn_hmma2_kernel,
                         cudaFuncAttributeMaxDynamicSharedMemorySize,
                         (int)smem_bytes);
    attn_hmma2_kernel<<<B, 128, smem_bytes>>>(x, Wq, Wk, Wv, out);
}

// round 5
// speedup vs baseline: 1.1321x; 1.1321x over previous
#include <cuda_runtime.h>
#include <cstdint>

// x [B=512, T=128, C=512] fp32; Wq/Wk/Wv [H=64, C=512]; out [B, T, 64] fp32.
// 256-thread CTA per batch. mma.sync m16n8k8 tf32.
// cp.async double-buffered projection tiles; balanced causal work split.
#define TT 128
#define CC 512
#define HH 64
#define KT 32

// pitches (floats); pitch % 32 == 4 => conflict-free fragment LDS
#define PT 36     // X/W staging tiles [rows][32] raw fp32
#define PQ 68     // Qs/Ks [128][64] tf32
#define PVT 132   // Vt [64][128] tf32
#define PS 132    // S/P [128][128]

// smem float offsets
#define OFF_Q   0
#define OFF_K   (128 * PQ)                    // 8704
#define OFF_VT  (2 * 128 * PQ)                // 17408
#define OFF_SCR (OFF_VT + 64 * PVT)           // 25856
#define OFF_S   OFF_SCR
#define XBUF(bf) (OFF_SCR + (bf) * (128 * PT))            // 2 x 4608
#define WBUF(bf) (OFF_SCR + 2 * 128 * PT + (bf) * (192 * PT)) // 2 x 6912
#define SMEM_FLOATS (OFF_SCR + 2 * 128 * PT + 2 * 192 * PT)   // 48896 = 195584 B

__device__ __forceinline__ float tf32r(float f) {
    uint32_t u;
    asm("cvt.rna.tf32.f32 %0, %1;" : "=r"(u) : "f"(f));
    return __uint_as_float(u);
}
__device__ __forceinline__ uint32_t tf32b(float f) {
    uint32_t u;
    asm("cvt.rna.tf32.f32 %0, %1;" : "=r"(u) : "f"(f));
    return u;
}
__device__ __forceinline__ uint32_t fb(float f) { return __float_as_uint(f); }

__device__ __forceinline__ uint32_t smem_u32(const void* p) {
    uint32_t a;
    asm("{ .reg .u64 t; cvta.to.shared.u64 t, %1; cvt.u32.u64 %0, t; }" : "=r"(a) : "l"(p));
    return a;
}
__device__ __forceinline__ void cp16(uint32_t dst, const float* src) {
    asm volatile("cp.async.ca.shared.global [%0], [%1], 16;" :: "r"(dst), "l"(src));
}
#define CP_COMMIT() asm volatile("cp.async.commit_group;" ::: "memory")
#define CP_WAIT1()  asm volatile("cp.async.wait_group 1;"  ::: "memory")
#define CP_WAIT0()  asm volatile("cp.async.wait_group 0;"  ::: "memory")

__device__ __forceinline__ void mma8(float* d, const uint32_t* a, const uint32_t* b) {
    asm volatile(
        "mma.sync.aligned.m16n8k8.row.col.f32.tf32.tf32.f32 "
        "{%0,%1,%2,%3}, {%4,%5,%6,%7}, {%8,%9}, {%0,%1,%2,%3};"
        : "+f"(d[0]), "+f"(d[1]), "+f"(d[2]), "+f"(d[3])
        : "r"(a[0]), "r"(a[1]), "r"(a[2]), "r"(a[3]), "r"(b[0]), "r"(b[1]));
}

__global__ __launch_bounds__(256, 1)
void attn_hmma3_kernel(const float* __restrict__ x,
                       const float* __restrict__ Wq,
                       const float* __restrict__ Wk,
                       const float* __restrict__ Wv,
                       float* __restrict__ out)
{
    extern __shared__ float sm[];
    float* Qs = sm + OFF_Q;
    float* Ks = sm + OFF_K;
    float* Vt = sm + OFF_VT;
    float* Ss = sm + OFF_S;
    const uint32_t sb = smem_u32(sm);

    const int tid  = threadIdx.x;
    const int wid  = tid >> 5;
    const int lane = tid & 31;
    const int l4   = lane >> 2;
    const int lk   = lane & 3;
    const int b    = blockIdx.x;
    const float* xb = x + (size_t)b * TT * CC;

    const int wr = wid >> 1;        // 0..3
    const int wc = wid & 1;         // 0..1
    // balanced causal row mapping: this warp owns row tiles {wr, 7-wr}
    const int rt0 = wr * 16;
    const int rt1 = (7 - wr) * 16;

    // --- cp.async tile stagers ---
    auto issue_chunk = [&](int ch, int bf) {
        const int k0 = ch * KT;
        const uint32_t xB = sb + XBUF(bf) * 4;
        const uint32_t wB = sb + WBUF(bf) * 4;
#pragma unroll
        for (int q = 0; q < 4; q++) {            // X tile [128][32]
            int idx = q * 256 + tid;
            int row = idx >> 3, c4 = idx & 7;
            cp16(xB + (uint32_t)(row * PT + c4 * 4) * 4, xb + row * CC + k0 + c4 * 4);
        }
#pragma unroll
        for (int q = 0; q < 6; q++) {            // W tile [192][32] = Wq|Wk|Wv
            int idx = q * 256 + tid;
            int row = idx >> 3, c4 = idx & 7;
            const float* Wp = (row < 64) ? (Wq + row * CC)
                            : (row < 128) ? (Wk + (row - 64) * CC)
                                          : (Wv + (row - 128) * CC);
            cp16(wB + (uint32_t)(row * PT + c4 * 4) * 4, Wp + k0 + c4 * 4);
        }
        CP_COMMIT();
    };

    // ============ Phase 1: [Q|K|V] = x @ W^T (16 chunks, double-buffered) ============
    float acc[2][12][4];
#pragma unroll
    for (int i = 0; i < 2; i++)
#pragma unroll
        for (int j = 0; j < 12; j++)
#pragma unroll
            for (int k = 0; k < 4; k++) acc[i][j][k] = 0.0f;

    const int nb1 = wc * 96;

    issue_chunk(0, 0);
    issue_chunk(1, 1);

#pragma unroll 1
    for (int ch = 0; ch < 16; ch++) {
        if (ch == 15) { CP_WAIT0(); } else { CP_WAIT1(); }
        __syncthreads();
        const int bf = ch & 1;
        const float* Xs  = sm + XBUF(bf);
        const float* Wsm = sm + WBUF(bf);

#pragma unroll
        for (int ks = 0; ks < 4; ks++) {
            const int kk = ks * 8;
            uint32_t a[2][4];
#pragma unroll
            for (int mt = 0; mt < 2; mt++) {
                const int rb = mt ? rt1 : rt0;
                const float* ap = Xs + (rb + l4) * PT + kk + lk;
                a[mt][0] = tf32b(ap[0]);
                a[mt][1] = tf32b(ap[8 * PT]);
                a[mt][2] = tf32b(ap[4]);
                a[mt][3] = tf32b(ap[8 * PT + 4]);
            }
#pragma unroll
            for (int nt = 0; nt < 12; nt++) {
                const float* bp = Wsm + (nb1 + nt * 8 + l4) * PT + kk + lk;
                uint32_t b2[2] = { tf32b(bp[0]), tf32b(bp[4]) };
                mma8(acc[0][nt], a[0], b2);
                mma8(acc[1][nt], a[1], b2);
            }
        }
        __syncthreads();
        if (ch < 14) issue_chunk(ch + 2, ch & 1);
    }

    // Epilogue: route D frags to Qs / Ks / Vt (tf32-rounded)
#pragma unroll
    for (int mt = 0; mt < 2; mt++) {
        const int r0 = (mt ? rt1 : rt0) + l4;
#pragma unroll
        for (int nt = 0; nt < 12; nt++) {
            const int c0 = nb1 + nt * 8 + 2 * lk;
            float d0 = tf32r(acc[mt][nt][0]), d1 = tf32r(acc[mt][nt][1]);
            float d2 = tf32r(acc[mt][nt][2]), d3 = tf32r(acc[mt][nt][3]);
            if (c0 < 64) {
                *reinterpret_cast<float2*>(Qs + r0 * PQ + c0)       = make_float2(d0, d1);
                *reinterpret_cast<float2*>(Qs + (r0 + 8) * PQ + c0) = make_float2(d2, d3);
            } else if (c0 < 128) {
                *reinterpret_cast<float2*>(Ks + r0 * PQ + (c0 - 64))       = make_float2(d0, d1);
                *reinterpret_cast<float2*>(Ks + (r0 + 8) * PQ + (c0 - 64)) = make_float2(d2, d3);
            } else {
                const int h = c0 - 128;
                Vt[h * PVT + r0]           = d0;
                Vt[(h + 1) * PVT + r0]     = d1;
                Vt[h * PVT + r0 + 8]       = d2;
                Vt[(h + 1) * PVT + r0 + 8] = d3;
            }
        }
    }
    __syncthreads();

    // ============ Phase 2: S = Q K^T — balanced causal tiles ============
    // warp owns col tiles nt = wc, wc+2, ... ; row tile i needs nt <= 2i+1
    {
        const int ntmax0 = 2 * wr + 1;           // for rt0 (always <= ntmax1)
        const int ntmax1 = 2 * (7 - wr) + 1;     // for rt1
        float accS0[8][4], accS1[8][4];
#pragma unroll
        for (int j = 0; j < 8; j++)
#pragma unroll
            for (int k = 0; k < 4; k++) { accS0[j][k] = 0.0f; accS1[j][k] = 0.0f; }

#pragma unroll
        for (int ks = 0; ks < 8; ks++) {
            const int kk = ks * 8;
            uint32_t a0[4], a1[4];
            {
                const float* ap = Qs + (rt0 + l4) * PQ + kk + lk;
                a0[0] = fb(ap[0]); a0[1] = fb(ap[8 * PQ]);
                a0[2] = fb(ap[4]); a0[3] = fb(ap[8 * PQ + 4]);
            }
            {
                const float* ap = Qs + (rt1 + l4) * PQ + kk + lk;
                a1[0] = fb(ap[0]); a1[1] = fb(ap[8 * PQ]);
                a1[2] = fb(ap[4]); a1[3] = fb(ap[8 * PQ + 4]);
            }
#pragma unroll
            for (int u = 0; u < 8; u++) {
                const int nt = wc + 2 * u;
                if (nt <= ntmax1) {
                    const float* bp = Ks + (nt * 8 + l4) * PQ + kk + lk;
                    uint32_t b2[2] = { fb(bp[0]), fb(bp[4]) };
                    mma8(accS1[u], a1, b2);
                    if (nt <= ntmax0) mma8(accS0[u], a0, b2);
                }
            }
        }
#pragma unroll
        for (int u = 0; u < 8; u++) {
            const int nt = wc + 2 * u;
            const int c0 = nt * 8 + 2 * lk;
            if (nt <= ntmax1) {
                const int r0 = rt1 + l4;
                *reinterpret_cast<float2*>(Ss + r0 * PS + c0) =
                    make_float2(accS1[u][0], accS1[u][1]);
                *reinterpret_cast<float2*>(Ss + (r0 + 8) * PS + c0) =
                    make_float2(accS1[u][2], accS1[u][3]);
            }
            if (nt <= ntmax0) {
                const int r0 = rt0 + l4;
                *reinterpret_cast<float2*>(Ss + r0 * PS + c0) =
                    make_float2(accS0[u][0], accS0[u][1]);
                *reinterpret_cast<float2*>(Ss + (r0 + 8) * PS + c0) =
                    make_float2(accS0[u][2], accS0[u][3]);
            }
        }
    }
    __syncthreads();

    // ============ Softmax (scale + causal mask), P stored tf32, normalized ============
    {
        for (int rr = 0; rr < 16; rr++) {
            const int r = wid * 16 + rr;
            float v0 = Ss[r * PS + lane];
            float v1 = Ss[r * PS + lane + 32];
            float v2 = Ss[r * PS + lane + 64];
            float v3 = Ss[r * PS + lane + 96];
            v0 = (lane      <= r) ? v0 * 0.125f : -1e30f;
            v1 = (lane + 32 <= r) ? v1 * 0.125f : -1e30f;
            v2 = (lane + 64 <= r) ? v2 * 0.125f : -1e30f;
            v3 = (lane + 96 <= r) ? v3 * 0.125f : -1e30f;
            float m = fmaxf(fmaxf(v0, v1), fmaxf(v2, v3));
#pragma unroll
            for (int o = 16; o > 0; o >>= 1)
                m = fmaxf(m, __shfl_xor_sync(0xffffffffu, m, o));
            float e0 = __expf(v0 - m), e1 = __expf(v1 - m);
            float e2 = __expf(v2 - m), e3 = __expf(v3 - m);
            float s = e0 + e1 + e2 + e3;
#pragma unroll
            for (int o = 16; o > 0; o >>= 1)
                s += __shfl_xor_sync(0xffffffffu, s, o);
            const float inv = 1.0f / s;
            Ss[r * PS + lane]      = tf32r(e0 * inv);
            Ss[r * PS + lane + 32] = tf32r(e1 * inv);
            Ss[r * PS + lane + 64] = tf32r(e2 * inv);
            Ss[r * PS + lane + 96] = tf32r(e3 * inv);
        }
    }
    __syncthreads();

    // ============ Phase 3: O = P @ V — skip all-zero P k-tiles ============
    {
        const int nb3 = wc * 32;
        const int ksmax0 = 2 * wr + 1;           // rows rt0: P zero beyond
        const int ksmax1 = 2 * (7 - wr) + 1;     // >= ksmax0
        float accO[2][4][4];
#pragma unroll
        for (int i = 0; i < 2; i++)
#pragma unroll
            for (int j = 0; j < 4; j++)
#pragma unroll
                for (int k = 0; k < 4; k++) accO[i][j][k] = 0.0f;

#pragma unroll
        for (int ks = 0; ks < 16; ks++) {
            if (ks <= ksmax1) {
                const int kk = ks * 8;
                uint32_t b2[4][2];
#pragma unroll
                for (int nt = 0; nt < 4; nt++) {
                    const float* bp = Vt + (nb3 + nt * 8 + l4) * PVT + kk + lk;
                    b2[nt][0] = fb(bp[0]); b2[nt][1] = fb(bp[4]);
                }
                uint32_t a1[4];
                {
                    const float* ap = Ss + (rt1 + l4) * PS + kk + lk;
                    a1[0] = fb(ap[0]); a1[1] = fb(ap[8 * PS]);
                    a1[2] = fb(ap[4]); a1[3] = fb(ap[8 * PS + 4]);
                }
#pragma unroll
                for (int nt = 0; nt < 4; nt++) mma8(accO[1][nt], a1, b2[nt]);
                if (ks <= ksmax0) {
                    uint32_t a0[4];
                    const float* ap = Ss + (rt0 + l4) * PS + kk + lk;
                    a0[0] = fb(ap[0]); a0[1] = fb(ap[8 * PS]);
                    a0[2] = fb(ap[4]); a0[3] = fb(ap[8 * PS + 4]);
#pragma unroll
                    for (int nt = 0; nt < 4; nt++) mma8(accO[0][nt], a0, b2[nt]);
                }
            }
        }

#pragma unroll
        for (int mt = 0; mt < 2; mt++) {
            const int r0 = (mt ? rt1 : rt0) + l4;
#pragma unroll
            for (int nt = 0; nt < 4; nt++) {
                const int c0 = nb3 + nt * 8 + 2 * lk;
                *reinterpret_cast<float2*>(out + ((size_t)b * TT + r0) * HH + c0) =
                    make_float2(accO[mt][nt][0], accO[mt][nt][1]);
                *reinterpret_cast<float2*>(out + ((size_t)b * TT + r0 + 8) * HH + c0) =
                    make_float2(accO[mt][nt][2], accO[mt][nt][3]);
            }
        }
    }
}

extern "C" void kernel_launch(void* const* d_in, const int* in_sizes, int n_in,
                              void* d_out, int out_size)
{
    const float* x  = (const float*)d_in[0];
    const float* Wq = (const float*)d_in[1];
    const float* Wk = (const float*)d_in[2];
    const float* Wv = (const float*)d_in[3];
    float* out = (float*)d_out;

    const int B = in_sizes[0] / (TT * CC);                         // 512
    const size_t smem_bytes = (size_t)SMEM_FLOATS * sizeof(float); // 195584

    cudaFuncSetAttribute(attn_hmma3_kernel,
                         cudaFuncAttributeMaxDynamicSharedMemorySize,
                         (int)smem_bytes);
    attn_hmma3_kernel<<<B, 256, smem_bytes>>>(x, Wq, Wk, Wv, out);
}